// round 9
// baseline (speedup 1.0000x reference)
#include <cuda_runtime.h>

#define NX 1024
#define NY 1024
#define NB 8
#define CH (NX*NY)
#define NBLOCKS (NY*NB)         // 8192, one row per CTA

// Physics constants
#define PR     0.71f
#define RA_PR  710.0f
#define HA2_PR 71.0f
#define PR_DA  7.1f
#define DIFF_C 1.6666666666666667f
#define QQ     0.1f
#define DTINV  100.0f
#define NPTS   8388608.0

__device__ double   g_partials[NBLOCKS];
__device__ unsigned g_count = 0;   // atomicInc wraps -> graph-replay safe

// x-halo via warp shuffle; warp-boundary lanes patch from global (L1 hit).
__device__ __forceinline__ void halo(float4 c, const float* __restrict__ rowp,
                                     int tid, int lane,
                                     float& lz, float& lw, float& rx, float& ry)
{
    lw = __shfl_up_sync(0xFFFFFFFFu, c.w, 1);
    lz = __shfl_up_sync(0xFFFFFFFFu, c.z, 1);
    rx = __shfl_down_sync(0xFFFFFFFFu, c.x, 1);
    ry = __shfl_down_sync(0xFFFFFFFFu, c.y, 1);
    if (lane == 0 && tid != 0) {
        float2 h = *(const float2*)(rowp + tid * 4 - 2);
        lz = h.x; lw = h.y;
    }
    if (lane == 31 && tid != 255) {
        float2 h = *(const float2*)(rowp + tid * 4 + 4);
        rx = h.x; ry = h.y;
    }
}

// x first+second tgrad for 4 points; E0..E7 = values at x0-2..x0+5. (verified)
__device__ __forceinline__ void xderiv(float4 c, float lz, float lw, float rx, float ry,
                                       int tid, float* dx, float* dxx)
{
    float E0 = lz, E1 = lw, E2 = c.x, E3 = c.y, E4 = c.z, E5 = c.w, E6 = rx, E7 = ry;
    if (tid == 0) {
        dx[0]  = E3 - E2;
        dx[1]  = 0.5f * (E4 - E2);
        dxx[0] = 0.5f * E4 - E3 + 0.5f * E2;
        dxx[1] = 0.25f * E5 - 0.75f * E3 + 0.5f * E2;
    } else {
        dx[0]  = 0.5f * (E3 - E1);
        dx[1]  = 0.5f * (E4 - E2);
        dxx[0] = 0.25f * (E4 - 2.0f * E2 + E0);
        dxx[1] = 0.25f * (E5 - 2.0f * E3 + E1);
    }
    if (tid == 255) {
        dx[2]  = 0.5f * (E5 - E3);
        dx[3]  = E5 - E4;
        dxx[2] = 0.5f * E5 - 0.75f * E4 + 0.25f * E2;
        dxx[3] = 0.5f * E5 - E4 + 0.5f * E3;
    } else {
        dx[2]  = 0.5f * (E5 - E3);
        dx[3]  = 0.5f * (E6 - E4);
        dxx[2] = 0.25f * (E6 - 2.0f * E4 + E2);
        dxx[3] = 0.25f * (E7 - 2.0f * E5 + E3);
    }
}

// dx only (for P channel)
__device__ __forceinline__ void xderiv1(float4 c, float lz, float lw, float rx, float ry,
                                        int tid, float* dx)
{
    float E1 = lw, E2 = c.x, E3 = c.y, E4 = c.z, E5 = c.w, E6 = rx;
    dx[1] = 0.5f * (E4 - E2);
    dx[2] = 0.5f * (E5 - E3);
    dx[0] = (tid == 0)   ? (E3 - E2) : 0.5f * (E3 - E1);
    dx[3] = (tid == 255) ? (E5 - E4) : 0.5f * (E6 - E4);
}

// Full derivative set for one channel row (flat: center + 4 y-rows + shuffled x-halo)
struct CD { float v[4], dx[4], dxx[4], dy[4], dyy[4]; };

__device__ __forceinline__ void chan(const float* __restrict__ chp,
                                     int tid, int lane, int y, int x0,
                                     int rM, int rP, float s1,
                                     int rA, int rB, float cA, float cC, float cB,
                                     CD& d)
{
    const float* rowp = chp + (size_t)y * NX;
    float4 c  = *(const float4*)(rowp + x0);
    float4 m  = *(const float4*)(chp + (size_t)rM * NX + x0);
    float4 p  = *(const float4*)(chp + (size_t)rP * NX + x0);
    float4 a  = *(const float4*)(chp + (size_t)rA * NX + x0);
    float4 bb = *(const float4*)(chp + (size_t)rB * NX + x0);
    float lz, lw, rx, ry;
    halo(c, rowp, tid, lane, lz, lw, rx, ry);
    xderiv(c, lz, lw, rx, ry, tid, d.dx, d.dxx);
    const float* C  = (const float*)&c;
    const float* M  = (const float*)&m;  const float* P_ = (const float*)&p;
    const float* A  = (const float*)&a;  const float* B_ = (const float*)&bb;
#pragma unroll
    for (int j = 0; j < 4; j++) {
        d.v[j]   = C[j];
        d.dy[j]  = s1 * (P_[j] - M[j]);
        d.dyy[j] = cA * A[j] + cC * C[j] + cB * B_[j];
    }
}

__global__ __launch_bounds__(256)
void physics_loss_kernel(const float* __restrict__ fno, const float* __restrict__ fne,
                         float* __restrict__ out)
{
    const int tid  = threadIdx.x;
    const int lane = tid & 31;
    const int y    = blockIdx.x;          // one row per CTA (flat, no loop)
    const int b    = blockIdx.y;
    const int x0   = tid * 4;

    const size_t base = (size_t)b * 4 * CH;
    const float* __restrict__ Uc = fne + base;
    const float* __restrict__ Vc = fne + base + CH;
    const float* __restrict__ Tc = fne + base + 2 * (size_t)CH;
    const float* __restrict__ Pc = fne + base + 3 * (size_t)CH;

    const int   rM = (y > 0) ? y - 1 : 0;
    const int   rP = (y < NY - 1) ? y + 1 : NY - 1;
    const float s1 = (y == 0 || y == NY - 1) ? 1.0f : 0.5f;

    int rA, rB; float cA, cC, cB;
    if      (y == 0)      { rA = 2;      cA = 0.5f;  cC = 0.5f;   rB = 1;      cB = -1.0f; }
    else if (y == 1)      { rA = 0;      cA = 0.5f;  cC = -0.75f; rB = 3;      cB = 0.25f; }
    else if (y == NY - 2) { rA = NY - 4; cA = 0.25f; cC = -0.75f; rB = NY - 1; cB = 0.5f;  }
    else if (y == NY - 1) { rA = NY - 3; cA = 0.5f;  cC = 0.5f;   rB = NY - 2; cB = -1.0f; }
    else                  { rA = y - 2;  cA = 0.25f; cC = -0.5f;  rB = y + 2;  cB = 0.25f; }

    const size_t rowo = (size_t)y * NX + x0;
    float acc = 0.0f;

    // ---- P pass: pdx, pdy ----
    float pdx[4], pdy[4];
    {
        const float* rowp = Pc + (size_t)y * NX;
        float4 c = *(const float4*)(rowp + x0);
        float4 m = *(const float4*)(Pc + (size_t)rM * NX + x0);
        float4 p = *(const float4*)(Pc + (size_t)rP * NX + x0);
        float lz, lw, rx, ry;
        halo(c, rowp, tid, lane, lz, lw, rx, ry);
        xderiv1(c, lz, lw, rx, ry, tid, pdx);
        const float* M = (const float*)&m; const float* P_ = (const float*)&p;
#pragma unroll
        for (int j = 0; j < 4; j++) pdy[j] = s1 * (P_[j] - M[j]);
    }

    // f_now U, V rows (streamed once)
    float4 uo4 = __ldcs((const float4*)(fno + base + rowo));
    float4 vo4 = __ldcs((const float4*)(fno + base + CH + rowo));
    const float* Uo = (const float*)&uo4;
    const float* Vo = (const float*)&vo4;

    float cont[4], resy[4];

    // ---- U pass ----
    {
        CD d;
        chan(Uc, tid, lane, y, x0, rM, rP, s1, rA, rB, cA, cC, cB, d);
#pragma unroll
        for (int j = 0; j < 4; j++) {
            float Un = d.v[j];
            float resx = (Un - Uo[j]) * DTINV + Un * d.dx[j] + Vo[j] * d.dy[j]
                         + pdx[j] - PR * (d.dxx[j] + d.dyy[j]) + PR_DA * Un;
            acc += resx * resx;
            cont[j] = d.dx[j];
        }
    }
    // ---- V pass ----
    {
        CD d;
        chan(Vc, tid, lane, y, x0, rM, rP, s1, rA, rB, cA, cC, cB, d);
#pragma unroll
        for (int j = 0; j < 4; j++) {
            float Vn = d.v[j];
            float cj = cont[j] + d.dy[j];
            acc += cj * cj;
            resy[j] = (Vn - Vo[j]) * DTINV + Uo[j] * d.dx[j] + Vn * d.dy[j]
                      + pdy[j] - PR * (d.dxx[j] + d.dyy[j]) + (HA2_PR + PR_DA) * Vn;
        }
    }
    // ---- T pass ----
    {
        CD d;
        chan(Tc, tid, lane, y, x0, rM, rP, s1, rA, rB, cA, cC, cB, d);
        float4 to4 = __ldcs((const float4*)(fno + base + 2 * (size_t)CH + rowo));
        const float* To = (const float*)&to4;
#pragma unroll
        for (int j = 0; j < 4; j++) {
            float Tn = d.v[j];
            float ry2 = resy[j] - RA_PR * Tn;
            acc += ry2 * ry2;
            float rest = (Tn - To[j]) * DTINV + Uo[j] * d.dx[j] + Vo[j] * d.dy[j]
                         - DIFF_C * (d.dxx[j] + d.dyy[j]) - QQ * Tn;
            acc += rest * rest;
        }
    }

    double dacc = (double)acc;

    // block reduction
#pragma unroll
    for (int o = 16; o > 0; o >>= 1)
        dacc += __shfl_xor_sync(0xFFFFFFFFu, dacc, o);

    __shared__ double ws[8];
    __shared__ bool   is_last;
    if (lane == 0) ws[tid >> 5] = dacc;
    __syncthreads();

    const int bid = blockIdx.y * NY + blockIdx.x;
    if (tid == 0) {
        double s = 0.0;
#pragma unroll
        for (int k = 0; k < 8; k++) s += ws[k];
        g_partials[bid] = s;
        __threadfence();
        unsigned prev = atomicInc(&g_count, NBLOCKS - 1);
        is_last = (prev == NBLOCKS - 1);
    }
    __syncthreads();

    // last CTA reduces all partials (8192/256 = 32 per thread)
    if (is_last) {
        double v = 0.0;
#pragma unroll
        for (int k = 0; k < NBLOCKS / 256; k++)
            v += g_partials[tid + k * 256];
#pragma unroll
        for (int o = 16; o > 0; o >>= 1)
            v += __shfl_xor_sync(0xFFFFFFFFu, v, o);
        if (lane == 0) ws[tid >> 5] = v;
        __syncthreads();
        if (tid == 0) {
            double s = 0.0;
#pragma unroll
            for (int k = 0; k < 8; k++) s += ws[k];
            double t = s * 1e-4 / NPTS;
            if (t < 1e-10) t = 1e-10;
            if (t > 1.0)   t = 1.0;
            out[0] = (float)t;
        }
    }
}

extern "C" void kernel_launch(void* const* d_in, const int* in_sizes, int n_in,
                              void* d_out, int out_size)
{
    const float* f_now  = (const float*)d_in[0];
    const float* f_next = (const float*)d_in[1];

    dim3 grid(NY, NB);
    physics_loss_kernel<<<grid, 256>>>(f_now, f_next, (float*)d_out);
}

// round 10
// speedup vs baseline: 1.5298x; 1.5298x over previous
#include <cuda_runtime.h>

#define NX 1024
#define NY 1024
#define NB 8
#define CH (NX*NY)
#define NBLOCKS (NY*NB)         // 8192, one row per CTA
#define NPTS 8388608.0

// Physics constants
#define PR     0.71f
#define RA_PR  710.0f
#define HA2_PR 71.0f
#define PR_DA  7.1f
#define DIFF_C 1.6666666666666667f
#define QQ     0.1f
#define DTINV  100.0f

__device__ double   g_partials[NBLOCKS];
__device__ unsigned g_count = 0;   // atomicInc wraps -> graph-replay safe

// tgrad along x at global index i; W[12] covers x0-4 .. x0+7, center at W[j+4]
__device__ __forceinline__ float d1x(const float* W, int j, int i) {
    if (i == 0)      return W[5] - W[4];
    if (i == NX - 1) return W[j + 4] - W[j + 3];
    return 0.5f * (W[j + 5] - W[j + 3]);
}

// tgrad(tgrad(f,x),x) at index i
__device__ __forceinline__ float d2x(const float* W, int j, int i) {
    if (i == 0)      return 0.5f * W[6] - W[5] + 0.5f * W[4];
    if (i == 1)      return 0.25f * W[7] - 0.75f * W[5] + 0.5f * W[4];
    if (i == NX - 2) return 0.5f * W[j + 5] - 0.75f * W[j + 4] + 0.25f * W[j + 2];
    if (i == NX - 1) return 0.5f * W[j + 4] - W[j + 3] + 0.5f * W[j + 2];
    return 0.25f * (W[j + 6] - 2.0f * W[j + 4] + W[j + 2]);
}

// 12-float x-window: plain predicated float4 loads (NO shuffles — see R9 post-mortem)
__device__ __forceinline__ void load_window(const float* __restrict__ row, int tid, int x0, float* W) {
    float4 c = *(const float4*)(row + x0);
    W[4] = c.x; W[5] = c.y; W[6] = c.z; W[7] = c.w;
    if (tid > 0) {
        float4 l = *(const float4*)(row + x0 - 4);
        W[0] = l.x; W[1] = l.y; W[2] = l.z; W[3] = l.w;
    } else { W[0] = W[1] = W[2] = W[3] = 0.0f; }
    if (tid < 255) {
        float4 r = *(const float4*)(row + x0 + 4);
        W[8] = r.x; W[9] = r.y; W[10] = r.z; W[11] = r.w;
    } else { W[8] = W[9] = W[10] = W[11] = 0.0f; }
}

struct Deriv { float v[4], dx[4], dy[4], dxx[4], dyy[4]; };

__device__ __forceinline__ void full_derivs(
    const float* __restrict__ ch, int tid, int y, int x0,
    int rM, int rP, float s1,
    int rA, int rB, float cA, float cC, float cB,
    Deriv& d)
{
    float W[12];
    load_window(ch + (size_t)y * NX, tid, x0, W);
    float4 m  = *(const float4*)(ch + (size_t)rM * NX + x0);
    float4 p  = *(const float4*)(ch + (size_t)rP * NX + x0);
    float4 a  = *(const float4*)(ch + (size_t)rA * NX + x0);
    float4 bb = *(const float4*)(ch + (size_t)rB * NX + x0);
    float mm[4]  = {m.x,  m.y,  m.z,  m.w};
    float pp[4]  = {p.x,  p.y,  p.z,  p.w};
    float aa[4]  = {a.x,  a.y,  a.z,  a.w};
    float bbv[4] = {bb.x, bb.y, bb.z, bb.w};
#pragma unroll
    for (int j = 0; j < 4; j++) {
        int i = x0 + j;
        d.v[j]   = W[j + 4];
        d.dx[j]  = d1x(W, j, i);
        d.dxx[j] = d2x(W, j, i);
        d.dy[j]  = s1 * (pp[j] - mm[j]);
        d.dyy[j] = cA * aa[j] + cC * W[j + 4] + cB * bbv[j];
    }
}

__global__ __launch_bounds__(256)
void physics_loss_kernel(const float* __restrict__ fno, const float* __restrict__ fne,
                         float* __restrict__ out)
{
    const int tid = threadIdx.x;
    const int y   = blockIdx.x;
    const int b   = blockIdx.y;
    const int x0  = tid * 4;

    // y-gradient rows + scale
    const int   rM = (y > 0) ? y - 1 : 0;
    const int   rP = (y < NY - 1) ? y + 1 : NY - 1;
    const float s1 = (y == 0 || y == NY - 1) ? 1.0f : 0.5f;

    int rA, rB; float cA, cC, cB;
    if      (y == 0)      { rA = 2;      cA = 0.5f;  cC = 0.5f;   rB = 1;      cB = -1.0f; }
    else if (y == 1)      { rA = 0;      cA = 0.5f;  cC = -0.75f; rB = 3;      cB = 0.25f; }
    else if (y == NY - 2) { rA = NY - 4; cA = 0.25f; cC = -0.75f; rB = NY - 1; cB = 0.5f;  }
    else if (y == NY - 1) { rA = NY - 3; cA = 0.5f;  cC = 0.5f;   rB = NY - 2; cB = -1.0f; }
    else                  { rA = y - 2;  cA = 0.25f; cC = -0.5f;  rB = y + 2;  cB = 0.25f; }

    const size_t base = (size_t)b * 4 * CH;
    const size_t rowo = (size_t)y * NX + x0;

    // f_now fields (U, V, T) — streamed once, evict-first
    float4 uo4 = __ldcs((const float4*)(fno + base + 0 * (size_t)CH + rowo));
    float4 vo4 = __ldcs((const float4*)(fno + base + 1 * (size_t)CH + rowo));
    float4 to4 = __ldcs((const float4*)(fno + base + 2 * (size_t)CH + rowo));
    float Uo[4] = {uo4.x, uo4.y, uo4.z, uo4.w};
    float Vo[4] = {vo4.x, vo4.y, vo4.z, vo4.w};
    float To[4] = {to4.x, to4.y, to4.z, to4.w};

    float cont[4], resx[4], resy[4], rest[4];

    Deriv D;
    // ---- U_next ----
    full_derivs(fne + base + 0 * (size_t)CH, tid, y, x0, rM, rP, s1, rA, rB, cA, cC, cB, D);
#pragma unroll
    for (int j = 0; j < 4; j++) {
        float Un = D.v[j];
        cont[j] = D.dx[j];
        resx[j] = (Un - Uo[j]) * DTINV + Un * D.dx[j] + Vo[j] * D.dy[j]
                  - PR * (D.dxx[j] + D.dyy[j]) + PR_DA * Un;
    }
    // ---- V_next ----
    full_derivs(fne + base + 1 * (size_t)CH, tid, y, x0, rM, rP, s1, rA, rB, cA, cC, cB, D);
#pragma unroll
    for (int j = 0; j < 4; j++) {
        float Vn = D.v[j];
        cont[j] += D.dy[j];
        resy[j] = (Vn - Vo[j]) * DTINV + Uo[j] * D.dx[j] + Vn * D.dy[j]
                  - PR * (D.dxx[j] + D.dyy[j]) + (HA2_PR + PR_DA) * Vn;
    }
    // ---- T_next ----
    full_derivs(fne + base + 2 * (size_t)CH, tid, y, x0, rM, rP, s1, rA, rB, cA, cC, cB, D);
#pragma unroll
    for (int j = 0; j < 4; j++) {
        float Tn = D.v[j];
        resy[j] -= RA_PR * Tn;
        rest[j] = (Tn - To[j]) * DTINV + Uo[j] * D.dx[j] + Vo[j] * D.dy[j]
                  - DIFF_C * (D.dxx[j] + D.dyy[j]) - QQ * Tn;
    }
    // ---- P_next (dx, dy only) ----
    {
        const float* Pc = fne + base + 3 * (size_t)CH;
        float W[12];
        load_window(Pc + (size_t)y * NX, tid, x0, W);
        float4 m = *(const float4*)(Pc + (size_t)rM * NX + x0);
        float4 p = *(const float4*)(Pc + (size_t)rP * NX + x0);
        float mm[4] = {m.x, m.y, m.z, m.w};
        float pp[4] = {p.x, p.y, p.z, p.w};
#pragma unroll
        for (int j = 0; j < 4; j++) {
            int i = x0 + j;
            resx[j] += d1x(W, j, i);
            resy[j] += s1 * (pp[j] - mm[j]);
        }
    }

    // accumulate squared residuals
    float acc = 0.0f;
#pragma unroll
    for (int j = 0; j < 4; j++) {
        acc += cont[j] * cont[j] + resx[j] * resx[j]
             + resy[j] * resy[j] + rest[j] * rest[j];
    }

    // block reduction
#pragma unroll
    for (int o = 16; o > 0; o >>= 1) acc += __shfl_xor_sync(0xFFFFFFFFu, acc, o);

    __shared__ double ws[8];
    __shared__ bool   is_last;
    if ((tid & 31) == 0) ws[tid >> 5] = (double)acc;
    __syncthreads();

    const int bid = blockIdx.y * NY + blockIdx.x;
    if (tid == 0) {
        double s = 0.0;
#pragma unroll
        for (int k = 0; k < 8; k++) s += ws[k];
        g_partials[bid] = s;
        __threadfence();
        unsigned prev = atomicInc(&g_count, NBLOCKS - 1);
        is_last = (prev == NBLOCKS - 1);
    }
    __syncthreads();

    // last CTA reduces all partials (8192/256 = 32 per thread)
    if (is_last) {
        double v = 0.0;
#pragma unroll
        for (int k = 0; k < NBLOCKS / 256; k++)
            v += g_partials[tid + k * 256];
#pragma unroll
        for (int o = 16; o > 0; o >>= 1)
            v += __shfl_xor_sync(0xFFFFFFFFu, v, o);
        if ((tid & 31) == 0) ws[tid >> 5] = v;
        __syncthreads();
        if (tid == 0) {
            double s = 0.0;
#pragma unroll
            for (int k = 0; k < 8; k++) s += ws[k];
            double t = s * 1e-4 / NPTS;
            if (t < 1e-10) t = 1e-10;
            if (t > 1.0)   t = 1.0;
            out[0] = (float)t;
        }
    }
}

extern "C" void kernel_launch(void* const* d_in, const int* in_sizes, int n_in,
                              void* d_out, int out_size)
{
    const float* f_now  = (const float*)d_in[0];
    const float* f_next = (const float*)d_in[1];

    dim3 grid(NY, NB);
    physics_loss_kernel<<<grid, 256>>>(f_now, f_next, (float*)d_out);
}